// round 6
// baseline (speedup 1.0000x reference)
#include <cuda_runtime.h>
#include <cuda_fp16.h>
#include <cstdint>

// Deformable conv2d B=8, Cin=Cout=128, H=W=64, 3x3 s1 p1 DG=1.
// f16 HMMA (fp32 accum), pair-interleaved fp16 X window, frag-ordered weight LDG,
// 1-barrier pipeline, 3 CTAs/SM. Grid: 512 = (b, ho).

#define THREADS 256
static constexpr int KTOT = 1152;
static constexpr int NSTEP = 48;        // 16 cg8 x 3 tb

// smem layout (bytes)
static constexpr int OFF_MI = 0;        // int[576]     2304
static constexpr int OFF_MW = 2304;     // float4[576]  9216
static constexpr int OFF_X  = 11520;    // 2 x (8ch x 10r x 68 u32) = 43520
static constexpr int OFF_B  = 55040;    // 2 x 864 u32 = 6912
static constexpr int SMEM_TOTAL = 61952;

static constexpr int XROWS = 10;
static constexpr int XST2  = 68;        // X row stride (u32 slots); 65 used
static constexpr int XCH2  = XROWS * XST2;  // 680
static constexpr int XWIN2 = 8 * XCH2;      // 5440 u32 per buffer
static constexpr int BST2  = 72;        // B row stride (u32)

// frag-ordered fp16 weights: [(slice*3+ks)*128 + co][tq], half2 = (ch even, ch odd)
__device__ uint32_t g_wtF[NSTEP * 3 * 128 * 4];

__device__ __forceinline__ void mma_f16(float* d, uint32_t a0, uint32_t a1,
                                        uint32_t b0) {
    asm volatile(
        "mma.sync.aligned.m16n8k8.row.col.f32.f16.f16.f32 "
        "{%0,%1,%2,%3}, {%4,%5}, {%6}, {%0,%1,%2,%3};"
        : "+f"(d[0]), "+f"(d[1]), "+f"(d[2]), "+f"(d[3])
        : "r"(a0), "r"(a1), "r"(b0));
}
__device__ __forceinline__ uint32_t h2u(__half2 h) { return *(uint32_t*)&h; }

__global__ void wt_permute(const float* __restrict__ w) {
    int idx = blockIdx.x * 256 + threadIdx.x;
    if (idx >= NSTEP * 3 * 128 * 4) return;
    int tq = idx & 3, co = (idx >> 2) & 127, rest = idx >> 9;
    int ks = rest % 3, slice = rest / 3;
    int cg8 = slice / 3, tb = slice % 3;
    int tap = tb * 3 + ks, ch0 = cg8 * 8 + 2 * tq;
    g_wtF[idx] = h2u(__floats2half2_rn(w[co * KTOT + ch0 * 9 + tap],
                                       w[co * KTOT + (ch0 + 1) * 9 + tap]));
}

// stage one float4 of an X window as interleaved half2 pairs PS[s]=(x[s-1],x[s])
__device__ __forceinline__ void stage_unit(uint32_t* xw, const float* xcb,
                                           int idx, int lo) {
    int ch = idx / (XROWS * 16), rr = idx - ch * (XROWS * 16);
    int r = rr >> 4, w4 = rr & 15;
    float4 f = *(const float4*)(xcb + ch * 4096 + (lo + r) * 64 + w4 * 4);
    float prev = __shfl_up_sync(0xffffffffu, f.w, 1);
    uint32_t* dst = xw + ch * XCH2 + r * XST2 + 4 * w4;
    *(uint4*)dst = make_uint4(h2u(__floats2half2_rn(prev, f.x)),
                              h2u(__floats2half2_rn(f.x, f.y)),
                              h2u(__floats2half2_rn(f.y, f.z)),
                              h2u(__floats2half2_rn(f.z, f.w)));
    if (w4 == 15) dst[4] = h2u(__floats2half2_rn(f.w, 0.f));
}

// gather one (tap,px) over 8 channels into B tile
__device__ __forceinline__ void gather_unit(const uint32_t* xw, const float* xcb,
                                            uint32_t* bD, const int* sMI,
                                            const float4* sMW, int t, int ptb,
                                            int lo) {
    const int px = t & 63, ti = t >> 6;
    int tap = (ptb * 3 + ti) * 64 + px;
    int mi = sMI[tap];
    float4 mw = sMW[tap];
    int cy0 = mi & 63, cy1 = (mi >> 6) & 63, sl = mi >> 12;
    int wr0 = cy0 - lo, wr1 = cy1 - lo;
    bool in0 = (unsigned)wr0 < (unsigned)XROWS;
    bool in1 = (unsigned)wr1 < (unsigned)XROWS;
    int wr0c = min(max(wr0, 0), XROWS - 1), wr1c = min(max(wr1, 0), XROWS - 1);
    const uint32_t* p0 = xw + wr0c * XST2 + sl;
    const uint32_t* p1 = xw + wr1c * XST2 + sl;
    uint32_t* bRow = bD + px;
    if (in0 && in1) {
        #pragma unroll
        for (int jj = 0; jj < 4; jj++) {
            float vv[2];
            #pragma unroll
            for (int h = 0; h < 2; h++) {
                int ch = 2 * jj + h;
                float2 t0 = __half22float2(*(const __half2*)&p0[ch * XCH2]);
                float2 t1 = __half22float2(*(const __half2*)&p1[ch * XCH2]);
                float v = mw.x * t0.x;
                v = fmaf(mw.y, t0.y, v);
                v = fmaf(mw.z, t1.x, v);
                vv[h] = fmaf(mw.w, t1.y, v);
            }
            bRow[(ti * 4 + jj) * BST2] = h2u(__floats2half2_rn(vv[0], vv[1]));
        }
    } else {  // rare: a sampled row falls outside the staged window
        int cx0 = min(max(sl - 1, 0), 63), cx1 = min(sl, 63);
        #pragma unroll
        for (int jj = 0; jj < 4; jj++) {
            float vv[2];
            #pragma unroll
            for (int h = 0; h < 2; h++) {
                int ch = 2 * jj + h;
                const float* xp = xcb + ch * 4096;
                float2 t0, t1;
                if (in0) t0 = __half22float2(*(const __half2*)&p0[ch * XCH2]);
                else     t0 = make_float2(xp[cy0 * 64 + cx0], xp[cy0 * 64 + cx1]);
                if (in1) t1 = __half22float2(*(const __half2*)&p1[ch * XCH2]);
                else     t1 = make_float2(xp[cy1 * 64 + cx0], xp[cy1 * 64 + cx1]);
                float v = mw.x * t0.x;
                v = fmaf(mw.y, t0.y, v);
                v = fmaf(mw.z, t1.x, v);
                vv[h] = fmaf(mw.w, t1.y, v);
            }
            bRow[(ti * 4 + jj) * BST2] = h2u(__floats2half2_rn(vv[0], vv[1]));
        }
    }
}

__global__ __launch_bounds__(THREADS, 3)
void deform_conv_f16p(const float* __restrict__ x,
                      const float* __restrict__ offs,
                      float* __restrict__ out) {
    extern __shared__ char smem[];
    int*      sMI = (int*)(smem + OFF_MI);
    float4*   sMW = (float4*)(smem + OFF_MW);
    uint32_t* sX  = (uint32_t*)(smem + OFF_X);
    uint32_t* sBu = (uint32_t*)(smem + OFF_B);

    const int t = threadIdx.x, lane = t & 31, warp = t >> 5;
    const int b = blockIdx.x >> 6, ho = blockIdx.x & 63;
    const int lo = min(max(ho - 4, 0), 64 - XROWS);
    const float* xg = x + b * 524288;

    // ---- tap metadata: 9 taps x 64 px (channel-invariant) ----
    const float* ob = offs + b * 18 * 4096;
    for (int i = t; i < 576; i += THREADS) {
        int k = i >> 6, p = i & 63;
        float dy = ob[(2 * k) * 4096 + ho * 64 + p];
        float dx = ob[(2 * k + 1) * 4096 + ho * 64 + p];
        float py = (float)(ho - 1 + k / 3) + dy;
        float px = (float)(p  - 1 + k % 3) + dx;
        float fy = floorf(py), fx = floorf(px);
        int y0 = (int)fy, x0 = (int)fx;
        float wy = py - fy, wx = px - fx;
        float wy1 = 1.f - wy, wx1 = 1.f - wx;
        float w00 = wy1 * wx1, w01 = wy1 * wx, w10 = wy * wx1, w11 = wy * wx;
        bool vy0 = (unsigned)y0       < 64u, vy1 = (unsigned)(y0 + 1) < 64u;
        bool vx0 = (unsigned)x0       < 64u, vx1 = (unsigned)(x0 + 1) < 64u;
        if (!(vy0 && vx0)) w00 = 0.f;
        if (!(vy0 && vx1)) w01 = 0.f;
        if (!(vy1 && vx0)) w10 = 0.f;
        if (!(vy1 && vx1)) w11 = 0.f;
        int cy0 = min(max(y0, 0), 63), cy1 = min(max(y0 + 1, 0), 63);
        int s   = min(max(x0, -1), 63) + 1;      // pair slot: PS[s]=(x[s-1],x[s])
        sMI[i] = cy0 | (cy1 << 6) | (s << 12);
        sMW[i] = make_float4(w00, w01, w10, w11);
    }

    // ---- prologue: X window 0 (all threads, 1280 float4) ----
    #pragma unroll
    for (int i = 0; i < 5; i++)
        stage_unit(sX, xg, i * THREADS + t, lo);
    __syncthreads();

    const int g = lane >> 2, tq = lane & 3;
    const int warpM = warp >> 1, warpN = warp & 1;
    float acc[2][4][4];
    #pragma unroll
    for (int m = 0; m < 2; m++)
        #pragma unroll
        for (int n = 0; n < 4; n++)
            #pragma unroll
            for (int c = 0; c < 4; c++) acc[m][n][c] = 0.f;

    // produce step 0 (gather only; A comes via LDG)
    if (warp < 6) gather_unit(sX, xg, sBu, sMI, sMW, t, 0, lo);

    // ---- main pipeline ----
    for (int s = 0; s < NSTEP; s++) {
        __syncthreads();   // B(s) + X window ready

        // MMA step s: 2 m-tiles x 4 n-tiles x 3 k8 steps
        {
            const uint32_t* bB = sBu + (s & 1) * 864 + warpN * 32 + g;
            #pragma unroll
            for (int ks = 0; ks < 3; ks++) {
                const uint32_t* ap =
                    g_wtF + (((s * 3 + ks) * 128 + warpM * 32) << 2) + lane;
                uint32_t a00 = __ldg(ap);
                uint32_t a01 = __ldg(ap + 32);
                uint32_t a10 = __ldg(ap + 64);
                uint32_t a11 = __ldg(ap + 96);
                const uint32_t* bU = bB + (ks * 4 + tq) * BST2;
                #pragma unroll
                for (int nt = 0; nt < 4; nt++) {
                    uint32_t b0 = bU[nt * 8];
                    mma_f16(acc[0][nt], a00, a01, b0);
                    mma_f16(acc[1][nt], a10, a11, b0);
                }
            }
        }

        if (s == NSTEP - 1) break;
        const int sp = s + 1;
        const int pcg = sp / 3, ptb = sp - pcg * 3;

        if (warp < 6) {
            gather_unit(sX + (pcg & 1) * XWIN2, xg + pcg * 8 * 4096,
                        sBu + (sp & 1) * 864, sMI, sMW, t, ptb, lo);
        } else {
            int s3q = s / 3, s3r = s - s3q * 3;
            if (s3r < 2 && s3q + 1 < 16) {
                const int c = s3q + 1;
                uint32_t* xwn = sX + (c & 1) * XWIN2;
                const float* xcb = xg + c * 8 * 4096;
                int t2 = t - 192;
                #pragma unroll
                for (int j = 0; j < 10; j++)
                    stage_unit(xwn, xcb, s3r * 640 + t2 + j * 64, lo);
            }
        }
    }

    // ---- epilogue: D[m=cout][n=px] -> global ----
    float* o = out + b * 524288 + ho * 64 + warpN * 32;
    #pragma unroll
    for (int mt = 0; mt < 2; mt++) {
        int row0 = warpM * 32 + mt * 16 + g;
        #pragma unroll
        for (int nt = 0; nt < 4; nt++) {
            int px = nt * 8 + 2 * tq;
            *(float2*)(o + row0 * 4096 + px) =
                make_float2(acc[mt][nt][0], acc[mt][nt][1]);
            *(float2*)(o + (row0 + 8) * 4096 + px) =
                make_float2(acc[mt][nt][2], acc[mt][nt][3]);
        }
    }
}

extern "C" void kernel_launch(void* const* d_in, const int* in_sizes, int n_in,
                              void* d_out, int out_size) {
    const float* x    = (const float*)d_in[0];
    const float* offs = (const float*)d_in[1];
    const float* wgt  = (const float*)d_in[2];
    wt_permute<<<(NSTEP * 3 * 128 * 4 + 255) / 256, 256>>>(wgt);
    cudaFuncSetAttribute(deform_conv_f16p,
                         cudaFuncAttributeMaxDynamicSharedMemorySize, SMEM_TOTAL);
    deform_conv_f16p<<<512, THREADS, SMEM_TOTAL>>>(x, offs, (float*)d_out);
}

// round 7
// speedup vs baseline: 1.0026x; 1.0026x over previous
#include <cuda_runtime.h>
#include <cuda_fp16.h>
#include <cstdint>

// Deformable conv2d B=8, Cin=Cout=128, H=W=64, 3x3 s1 p1 DG=1.
// f16 HMMA (fp32 accum), pair-interleaved fp16 X window, frag-ordered weight LDG.
// In-step software pipeline: gather loads for step s+1 issue BEFORE MMA(s).
// Grid: 512 = (b, ho), 2 CTAs/SM.

#define THREADS 256
static constexpr int KTOT = 1152;
static constexpr int NSTEP = 48;        // 16 cg8 x 3 tb

// smem layout (bytes)
static constexpr int OFF_MI = 0;        // int[576]     2304
static constexpr int OFF_MW = 2304;     // float4[576]  9216
static constexpr int OFF_X  = 11520;    // 2 x (8ch x 12r x 68 u32) = 52224
static constexpr int OFF_B  = 63744;    // 2 x 864 u32 = 6912
static constexpr int SMEM_TOTAL = 70656;

static constexpr int XROWS = 12;
static constexpr int XST2  = 68;            // X row stride (u32 slots); 65 used
static constexpr int XCH2  = XROWS * XST2;  // 816
static constexpr int XWIN2 = 8 * XCH2;      // 6528 u32 per buffer
static constexpr int BST2  = 72;            // B row stride (u32)

// frag-ordered fp16 weights: [(slice*3+ks)*128 + co][tq], half2 = (ch even, ch odd)
__device__ uint32_t g_wtF[NSTEP * 3 * 128 * 4];

__device__ __forceinline__ void mma_f16(float* d, uint32_t a0, uint32_t a1,
                                        uint32_t b0) {
    asm volatile(
        "mma.sync.aligned.m16n8k8.row.col.f32.f16.f16.f32 "
        "{%0,%1,%2,%3}, {%4,%5}, {%6}, {%0,%1,%2,%3};"
        : "+f"(d[0]), "+f"(d[1]), "+f"(d[2]), "+f"(d[3])
        : "r"(a0), "r"(a1), "r"(b0));
}
__device__ __forceinline__ uint32_t h2u(__half2 h) { return *(uint32_t*)&h; }

__global__ void wt_permute(const float* __restrict__ w) {
    int idx = blockIdx.x * 256 + threadIdx.x;
    if (idx >= NSTEP * 3 * 128 * 4) return;
    int tq = idx & 3, co = (idx >> 2) & 127, rest = idx >> 9;
    int ks = rest % 3, slice = rest / 3;
    int cg8 = slice / 3, tb = slice % 3;
    int tap = tb * 3 + ks, ch0 = cg8 * 8 + 2 * tq;
    g_wtF[idx] = h2u(__floats2half2_rn(w[co * KTOT + ch0 * 9 + tap],
                                       w[co * KTOT + (ch0 + 1) * 9 + tap]));
}

// stage one float4 of an X window as interleaved half2 pairs PS[s]=(x[s-1],x[s])
__device__ __forceinline__ void stage_unit(uint32_t* xw, const float* xcb,
                                           int idx, int lo) {
    int ch = idx / (XROWS * 16), rr = idx - ch * (XROWS * 16);
    int r = rr >> 4, w4 = rr & 15;
    float4 f = *(const float4*)(xcb + ch * 4096 + (lo + r) * 64 + w4 * 4);
    float prev = __shfl_up_sync(0xffffffffu, f.w, 1);
    uint32_t* dst = xw + ch * XCH2 + r * XST2 + 4 * w4;
    *(uint4*)dst = make_uint4(h2u(__floats2half2_rn(prev, f.x)),
                              h2u(__floats2half2_rn(f.x, f.y)),
                              h2u(__floats2half2_rn(f.y, f.z)),
                              h2u(__floats2half2_rn(f.z, f.w)));
    if (w4 == 15) dst[4] = h2u(__floats2half2_rn(f.w, 0.f));
}

// full gather (used only for step 0 and the rare out-of-window path)
__device__ __forceinline__ void gather_full(const uint32_t* xw, const float* xcb,
                                            uint32_t* bD, const int* sMI,
                                            const float4* sMW, int t, int ptb,
                                            int lo) {
    const int px = t & 63, ti = t >> 6;
    int tap = (ptb * 3 + ti) * 64 + px;
    int mi = sMI[tap];
    float4 mw = sMW[tap];
    int cy0 = mi & 63, cy1 = (mi >> 6) & 63, sl = mi >> 12;
    int wr0 = cy0 - lo, wr1 = cy1 - lo;
    bool in0 = (unsigned)wr0 < (unsigned)XROWS;
    bool in1 = (unsigned)wr1 < (unsigned)XROWS;
    int wr0c = min(max(wr0, 0), XROWS - 1), wr1c = min(max(wr1, 0), XROWS - 1);
    const uint32_t* p0 = xw + wr0c * XST2 + sl;
    const uint32_t* p1 = xw + wr1c * XST2 + sl;
    int cx0 = min(max(sl - 1, 0), 63), cx1 = min(sl, 63);
    uint32_t* bRow = bD + px;
    #pragma unroll
    for (int jj = 0; jj < 4; jj++) {
        float vv[2];
        #pragma unroll
        for (int h = 0; h < 2; h++) {
            int ch = 2 * jj + h;
            const float* xp = xcb + ch * 4096;
            float2 t0, t1;
            if (in0) t0 = __half22float2(*(const __half2*)&p0[ch * XCH2]);
            else     t0 = make_float2(xp[cy0 * 64 + cx0], xp[cy0 * 64 + cx1]);
            if (in1) t1 = __half22float2(*(const __half2*)&p1[ch * XCH2]);
            else     t1 = make_float2(xp[cy1 * 64 + cx0], xp[cy1 * 64 + cx1]);
            float v = mw.x * t0.x;
            v = fmaf(mw.y, t0.y, v);
            v = fmaf(mw.z, t1.x, v);
            vv[h] = fmaf(mw.w, t1.y, v);
        }
        bRow[(ti * 4 + jj) * BST2] = h2u(__floats2half2_rn(vv[0], vv[1]));
    }
}

__global__ __launch_bounds__(THREADS, 2)
void deform_conv_f16p(const float* __restrict__ x,
                      const float* __restrict__ offs,
                      float* __restrict__ out) {
    extern __shared__ char smem[];
    int*      sMI = (int*)(smem + OFF_MI);
    float4*   sMW = (float4*)(smem + OFF_MW);
    uint32_t* sX  = (uint32_t*)(smem + OFF_X);
    uint32_t* sBu = (uint32_t*)(smem + OFF_B);

    const int t = threadIdx.x, lane = t & 31, warp = t >> 5;
    const int b = blockIdx.x >> 6, ho = blockIdx.x & 63;
    const int lo = min(max(ho - 5, 0), 64 - XROWS);
    const float* xg = x + b * 524288;

    // ---- tap metadata: 9 taps x 64 px (channel-invariant) ----
    const float* ob = offs + b * 18 * 4096;
    for (int i = t; i < 576; i += THREADS) {
        int k = i >> 6, p = i & 63;
        float dy = ob[(2 * k) * 4096 + ho * 64 + p];
        float dx = ob[(2 * k + 1) * 4096 + ho * 64 + p];
        float py = (float)(ho - 1 + k / 3) + dy;
        float px = (float)(p  - 1 + k % 3) + dx;
        float fy = floorf(py), fx = floorf(px);
        int y0 = (int)fy, x0 = (int)fx;
        float wy = py - fy, wx = px - fx;
        float wy1 = 1.f - wy, wx1 = 1.f - wx;
        float w00 = wy1 * wx1, w01 = wy1 * wx, w10 = wy * wx1, w11 = wy * wx;
        bool vy0 = (unsigned)y0       < 64u, vy1 = (unsigned)(y0 + 1) < 64u;
        bool vx0 = (unsigned)x0       < 64u, vx1 = (unsigned)(x0 + 1) < 64u;
        if (!(vy0 && vx0)) w00 = 0.f;
        if (!(vy0 && vx1)) w01 = 0.f;
        if (!(vy1 && vx0)) w10 = 0.f;
        if (!(vy1 && vx1)) w11 = 0.f;
        int cy0 = min(max(y0, 0), 63), cy1 = min(max(y0 + 1, 0), 63);
        int s   = min(max(x0, -1), 63) + 1;      // pair slot: PS[s]=(x[s-1],x[s])
        sMI[i] = cy0 | (cy1 << 6) | (s << 12);
        sMW[i] = make_float4(w00, w01, w10, w11);
    }

    // ---- prologue: X window 0 (all threads, 1536 float4) ----
    #pragma unroll
    for (int i = 0; i < 6; i++)
        stage_unit(sX, xg, i * THREADS + t, lo);
    __syncthreads();

    const int g = lane >> 2, tq = lane & 3;
    const int warpM = warp >> 1, warpN = warp & 1;
    float acc[2][4][4];
    #pragma unroll
    for (int m = 0; m < 2; m++)
        #pragma unroll
        for (int n = 0; n < 4; n++)
            #pragma unroll
            for (int c = 0; c < 4; c++) acc[m][n][c] = 0.f;

    // produce step 0
    if (warp < 6) gather_full(sX, xg, sBu, sMI, sMW, t, 0, lo);

    // ---- main pipeline ----
    for (int s = 0; s < NSTEP; s++) {
        __syncthreads();   // B(s) + X windows ready

        // ---- phase A: prefetch gather inputs for step s+1 (before MMA) ----
        const int sp = s + 1;
        const int pcg = sp / 3, ptb = sp - pcg * 3;
        const bool doG = (warp < 6) && (s < NSTEP - 1);
        uint32_t q0[8], q1[8];
        float4 mw;
        int cy0, cy1, sl;
        bool fast = false;
        const uint32_t* xw_p = sX + (pcg & 1) * XWIN2;
        const float* xcb_p = xg + pcg * 8 * 4096;
        if (doG) {
            int px = t & 63, ti = t >> 6;
            int tap = (ptb * 3 + ti) * 64 + px;
            int mi = sMI[tap];
            mw = sMW[tap];
            cy0 = mi & 63; cy1 = (mi >> 6) & 63; sl = mi >> 12;
            int wr0 = cy0 - lo, wr1 = cy1 - lo;
            bool in0 = (unsigned)wr0 < (unsigned)XROWS;
            bool in1 = (unsigned)wr1 < (unsigned)XROWS;
            fast = in0 && in1;
            int wr0c = min(max(wr0, 0), XROWS - 1);
            int wr1c = min(max(wr1, 0), XROWS - 1);
            const uint32_t* p0 = xw_p + wr0c * XST2 + sl;
            const uint32_t* p1 = xw_p + wr1c * XST2 + sl;
            #pragma unroll
            for (int ch = 0; ch < 8; ch++) {
                q0[ch] = p0[ch * XCH2];
                q1[ch] = p1[ch * XCH2];
            }
        }

        // ---- MMA step s: 2 m-tiles x 4 n-tiles x 3 k8 steps ----
        {
            const uint32_t* bB = sBu + (s & 1) * 864 + warpN * 32 + g;
            #pragma unroll
            for (int ks = 0; ks < 3; ks++) {
                const uint32_t* ap =
                    g_wtF + (((s * 3 + ks) * 128 + warpM * 32) << 2) + lane;
                uint32_t a00 = __ldg(ap);
                uint32_t a01 = __ldg(ap + 32);
                uint32_t a10 = __ldg(ap + 64);
                uint32_t a11 = __ldg(ap + 96);
                const uint32_t* bU = bB + (ks * 4 + tq) * BST2;
                #pragma unroll
                for (int nt = 0; nt < 4; nt++) {
                    uint32_t b0 = bU[nt * 8];
                    mma_f16(acc[0][nt], a00, a01, b0);
                    mma_f16(acc[1][nt], a10, a11, b0);
                }
            }
        }

        // ---- phase B: finish gather / stage X ----
        if (doG) {
            uint32_t* bD = sBu + (sp & 1) * 864;
            const int px = t & 63, ti = t >> 6;
            uint32_t* bRow = bD + px;
            if (fast) {
                #pragma unroll
                for (int jj = 0; jj < 4; jj++) {
                    float vv[2];
                    #pragma unroll
                    for (int h = 0; h < 2; h++) {
                        int ch = 2 * jj + h;
                        float2 t0 = __half22float2(*(const __half2*)&q0[ch]);
                        float2 t1 = __half22float2(*(const __half2*)&q1[ch]);
                        float v = mw.x * t0.x;
                        v = fmaf(mw.y, t0.y, v);
                        v = fmaf(mw.z, t1.x, v);
                        vv[h] = fmaf(mw.w, t1.y, v);
                    }
                    bRow[(ti * 4 + jj) * BST2] = h2u(__floats2half2_rn(vv[0], vv[1]));
                }
            } else {  // rare: a sampled row outside the staged window
                int cx0 = min(max(sl - 1, 0), 63), cx1 = min(sl, 63);
                bool in0 = (unsigned)(cy0 - lo) < (unsigned)XROWS;
                bool in1 = (unsigned)(cy1 - lo) < (unsigned)XROWS;
                #pragma unroll
                for (int jj = 0; jj < 4; jj++) {
                    float vv[2];
                    #pragma unroll
                    for (int h = 0; h < 2; h++) {
                        int ch = 2 * jj + h;
                        const float* xp = xcb_p + ch * 4096;
                        float2 t0, t1;
                        if (in0) t0 = __half22float2(*(const __half2*)&q0[ch]);
                        else     t0 = make_float2(xp[cy0 * 64 + cx0], xp[cy0 * 64 + cx1]);
                        if (in1) t1 = __half22float2(*(const __half2*)&q1[ch]);
                        else     t1 = make_float2(xp[cy1 * 64 + cx0], xp[cy1 * 64 + cx1]);
                        float v = mw.x * t0.x;
                        v = fmaf(mw.y, t0.y, v);
                        v = fmaf(mw.z, t1.x, v);
                        vv[h] = fmaf(mw.w, t1.y, v);
                    }
                    bRow[(ti * 4 + jj) * BST2] = h2u(__floats2half2_rn(vv[0], vv[1]));
                }
            }
        } else if (warp >= 6 && s < NSTEP - 1) {
            int s3q = s / 3, s3r = s - s3q * 3;
            if (s3r < 2 && s3q + 1 < 16) {
                const int c = s3q + 1;
                uint32_t* xwn = sX + (c & 1) * XWIN2;
                const float* xcb = xg + c * 8 * 4096;
                int t2 = t - 192;
                #pragma unroll
                for (int j = 0; j < 12; j++)
                    stage_unit(xwn, xcb, s3r * 768 + t2 + j * 64, lo);
            }
        }
    }

    // ---- epilogue: D[m=cout][n=px] -> global ----
    float* o = out + b * 524288 + ho * 64 + warpN * 32;
    #pragma unroll
    for (int mt = 0; mt < 2; mt++) {
        int row0 = warpM * 32 + mt * 16 + g;
        #pragma unroll
        for (int nt = 0; nt < 4; nt++) {
            int px = nt * 8 + 2 * tq;
            *(float2*)(o + row0 * 4096 + px) =
                make_float2(acc[mt][nt][0], acc[mt][nt][1]);
            *(float2*)(o + (row0 + 8) * 4096 + px) =
                make_float2(acc[mt][nt][2], acc[mt][nt][3]);
        }
    }
}

extern "C" void kernel_launch(void* const* d_in, const int* in_sizes, int n_in,
                              void* d_out, int out_size) {
    const float* x    = (const float*)d_in[0];
    const float* offs = (const float*)d_in[1];
    const float* wgt  = (const float*)d_in[2];
    wt_permute<<<(NSTEP * 3 * 128 * 4 + 255) / 256, 256>>>(wgt);
    cudaFuncSetAttribute(deform_conv_f16p,
                         cudaFuncAttributeMaxDynamicSharedMemorySize, SMEM_TOTAL);
    deform_conv_f16p<<<512, THREADS, SMEM_TOTAL>>>(x, offs, (float*)d_out);
}

// round 8
// speedup vs baseline: 1.3402x; 1.3368x over previous
#include <cuda_runtime.h>
#include <cuda_fp16.h>
#include <cstdint>

// Deformable conv2d B=8, Cin=Cout=128, H=W=64, 3x3 s1 p1 DG=1.
// f16 HMMA (fp32 accum), pair-interleaved fp16 X window, frag-ordered weight LDG.
// One CTA per (b, ho-pair): 256 CTAs, N=128 (2 output rows), single wave.

#define THREADS 256
static constexpr int KTOT = 1152;
static constexpr int NSTEP = 48;        // 16 cg8 x 3 tb (K=24 per step)

static constexpr int XROWS = 13;
static constexpr int XST2  = 68;            // X row stride (u32 slots)
static constexpr int XCH2  = XROWS * XST2;  // 884
static constexpr int XWIN2 = 8 * XCH2;      // 7072 u32 per buffer
static constexpr int BST2  = 136;           // B row stride (u32): 136%32=8 -> 8tq+g banks
static constexpr int BBUF  = 12 * BST2;     // 1632 u32 per buffer

// smem layout (bytes)
static constexpr int OFF_MI = 0;            // int[1152]     4608
static constexpr int OFF_MW = 4608;         // float4[1152] 18432
static constexpr int OFF_X  = 23040;        // 2 x 7072 u32 56576
static constexpr int OFF_B  = 79616;        // 2 x 1632 u32 13056
static constexpr int SMEM_TOTAL = 92672;

// frag-ordered fp16 weights: [(slice*3+ks)*128 + co][tq], half2 = (ch even, ch odd)
__device__ uint32_t g_wtF[NSTEP * 3 * 128 * 4];

__device__ __forceinline__ void mma_f16(float* d, uint32_t a0, uint32_t a1,
                                        uint32_t b0) {
    asm volatile(
        "mma.sync.aligned.m16n8k8.row.col.f32.f16.f16.f32 "
        "{%0,%1,%2,%3}, {%4,%5}, {%6}, {%0,%1,%2,%3};"
        : "+f"(d[0]), "+f"(d[1]), "+f"(d[2]), "+f"(d[3])
        : "r"(a0), "r"(a1), "r"(b0));
}
__device__ __forceinline__ uint32_t h2u(__half2 h) { return *(uint32_t*)&h; }

__global__ void wt_permute(const float* __restrict__ w) {
    int idx = blockIdx.x * 256 + threadIdx.x;
    if (idx >= NSTEP * 3 * 128 * 4) return;
    int tq = idx & 3, co = (idx >> 2) & 127, rest = idx >> 9;
    int ks = rest % 3, slice = rest / 3;
    int cg8 = slice / 3, tb = slice % 3;
    int tap = tb * 3 + ks, ch0 = cg8 * 8 + 2 * tq;
    g_wtF[idx] = h2u(__floats2half2_rn(w[co * KTOT + ch0 * 9 + tap],
                                       w[co * KTOT + (ch0 + 1) * 9 + tap]));
}

// stage one float4 of an X window as interleaved half2 pairs PS[s]=(x[s-1],x[s])
__device__ __forceinline__ void stage_unit(uint32_t* xw, const float* xcb,
                                           int idx, int lo) {
    int ch = idx / (XROWS * 16), rr = idx - ch * (XROWS * 16);
    int r = rr >> 4, w4 = rr & 15;
    float4 f = *(const float4*)(xcb + ch * 4096 + (lo + r) * 64 + w4 * 4);
    float prev = __shfl_up_sync(0xffffffffu, f.w, 1);
    uint32_t* dst = xw + ch * XCH2 + r * XST2 + 4 * w4;
    *(uint4*)dst = make_uint4(h2u(__floats2half2_rn(prev, f.x)),
                              h2u(__floats2half2_rn(f.x, f.y)),
                              h2u(__floats2half2_rn(f.y, f.z)),
                              h2u(__floats2half2_rn(f.z, f.w)));
    if (w4 == 15) dst[4] = h2u(__floats2half2_rn(f.w, 0.f));
}

// gather one (tap, px) unit over 8 channels into the B tile
__device__ __forceinline__ void gather_unit(const uint32_t* xw, const float* xcb,
                                            uint32_t* bD, const int* sMI,
                                            const float4* sMW, int idx, int ptb,
                                            int lo) {
    const int px = idx & 127, ti = idx >> 7;
    int tap = (ptb * 3 + ti) * 128 + px;
    int mi = sMI[tap];
    float4 mw = sMW[tap];
    int cy0 = mi & 63, cy1 = (mi >> 6) & 63, sl = mi >> 12;
    int wr0 = cy0 - lo, wr1 = cy1 - lo;
    bool in0 = (unsigned)wr0 < (unsigned)XROWS;
    bool in1 = (unsigned)wr1 < (unsigned)XROWS;
    int wr0c = min(max(wr0, 0), XROWS - 1), wr1c = min(max(wr1, 0), XROWS - 1);
    const uint32_t* p0 = xw + wr0c * XST2 + sl;
    const uint32_t* p1 = xw + wr1c * XST2 + sl;
    uint32_t* bRow = bD + px;
    if (in0 && in1) {
        #pragma unroll
        for (int jj = 0; jj < 4; jj++) {
            float vv[2];
            #pragma unroll
            for (int h = 0; h < 2; h++) {
                int ch = 2 * jj + h;
                float2 t0 = __half22float2(*(const __half2*)&p0[ch * XCH2]);
                float2 t1 = __half22float2(*(const __half2*)&p1[ch * XCH2]);
                float v = mw.x * t0.x;
                v = fmaf(mw.y, t0.y, v);
                v = fmaf(mw.z, t1.x, v);
                vv[h] = fmaf(mw.w, t1.y, v);
            }
            bRow[(ti * 4 + jj) * BST2] = h2u(__floats2half2_rn(vv[0], vv[1]));
        }
    } else {  // rare: a sampled row falls outside the staged window
        int cx0 = min(max(sl - 1, 0), 63), cx1 = min(sl, 63);
        #pragma unroll
        for (int jj = 0; jj < 4; jj++) {
            float vv[2];
            #pragma unroll
            for (int h = 0; h < 2; h++) {
                int ch = 2 * jj + h;
                const float* xp = xcb + ch * 4096;
                float2 t0, t1;
                if (in0) t0 = __half22float2(*(const __half2*)&p0[ch * XCH2]);
                else     t0 = make_float2(xp[cy0 * 64 + cx0], xp[cy0 * 64 + cx1]);
                if (in1) t1 = __half22float2(*(const __half2*)&p1[ch * XCH2]);
                else     t1 = make_float2(xp[cy1 * 64 + cx0], xp[cy1 * 64 + cx1]);
                float v = mw.x * t0.x;
                v = fmaf(mw.y, t0.y, v);
                v = fmaf(mw.z, t1.x, v);
                vv[h] = fmaf(mw.w, t1.y, v);
            }
            bRow[(ti * 4 + jj) * BST2] = h2u(__floats2half2_rn(vv[0], vv[1]));
        }
    }
}

__global__ __launch_bounds__(THREADS, 2)
void deform_conv_f16w(const float* __restrict__ x,
                      const float* __restrict__ offs,
                      float* __restrict__ out) {
    extern __shared__ char smem[];
    int*      sMI = (int*)(smem + OFF_MI);
    float4*   sMW = (float4*)(smem + OFF_MW);
    uint32_t* sX  = (uint32_t*)(smem + OFF_X);
    uint32_t* sBu = (uint32_t*)(smem + OFF_B);

    const int t = threadIdx.x, lane = t & 31, warp = t >> 5;
    const int b = blockIdx.x >> 5, ho2 = blockIdx.x & 31;
    const int lo = min(max(2 * ho2 - 5, 0), 64 - XROWS);
    const float* xg = x + b * 524288;

    // ---- tap metadata: 9 taps x 2 rows x 64 px ----
    const float* ob = offs + b * 18 * 4096;
    for (int i = t; i < 1152; i += THREADS) {
        int k = i >> 7, rp = i & 127, r = rp >> 6, p = rp & 63;
        int ho = 2 * ho2 + r;
        float dy = ob[(2 * k) * 4096 + ho * 64 + p];
        float dx = ob[(2 * k + 1) * 4096 + ho * 64 + p];
        float py = (float)(ho - 1 + k / 3) + dy;
        float px = (float)(p  - 1 + k % 3) + dx;
        float fy = floorf(py), fx = floorf(px);
        int y0 = (int)fy, x0 = (int)fx;
        float wy = py - fy, wx = px - fx;
        float wy1 = 1.f - wy, wx1 = 1.f - wx;
        float w00 = wy1 * wx1, w01 = wy1 * wx, w10 = wy * wx1, w11 = wy * wx;
        bool vy0 = (unsigned)y0       < 64u, vy1 = (unsigned)(y0 + 1) < 64u;
        bool vx0 = (unsigned)x0       < 64u, vx1 = (unsigned)(x0 + 1) < 64u;
        if (!(vy0 && vx0)) w00 = 0.f;
        if (!(vy0 && vx1)) w01 = 0.f;
        if (!(vy1 && vx0)) w10 = 0.f;
        if (!(vy1 && vx1)) w11 = 0.f;
        int cy0 = min(max(y0, 0), 63), cy1 = min(max(y0 + 1, 0), 63);
        int s   = min(max(x0, -1), 63) + 1;      // pair slot: PS[s]=(x[s-1],x[s])
        sMI[i] = cy0 | (cy1 << 6) | (s << 12);
        sMW[i] = make_float4(w00, w01, w10, w11);
    }

    // ---- prologue: X window 0 (1664 float4 over 256 threads) ----
    #pragma unroll
    for (int i = 0; i < 7; i++) {
        int idx = i * THREADS + t;
        if (idx < 8 * XROWS * 16) stage_unit(sX, xg, idx, lo);
    }
    __syncthreads();

    const int g = lane >> 2, tq = lane & 3;
    const int warpM = warp >> 1, warpN = warp & 1;   // M slab 32, N half 64
    float acc[2][8][4];
    #pragma unroll
    for (int m = 0; m < 2; m++)
        #pragma unroll
        for (int n = 0; n < 8; n++)
            #pragma unroll
            for (int c = 0; c < 4; c++) acc[m][n][c] = 0.f;

    // produce step 0 (2 units per gather thread)
    if (warp < 6) {
        gather_unit(sX, xg, sBu, sMI, sMW, t, 0, lo);
        gather_unit(sX, xg, sBu, sMI, sMW, 192 + t, 0, lo);
    }

    // ---- main pipeline ----
    for (int s = 0; s < NSTEP; s++) {
        __syncthreads();   // B(s) + X windows ready

        // MMA step s: 2 m-tiles x 8 n-tiles x 3 k8 steps
        {
            const uint32_t* bB = sBu + (s & 1) * BBUF + warpN * 64 + g;
            #pragma unroll
            for (int ks = 0; ks < 3; ks++) {
                const uint32_t* ap =
                    g_wtF + (((s * 3 + ks) * 128 + warpM * 32) << 2) + lane;
                uint32_t a00 = __ldg(ap);
                uint32_t a01 = __ldg(ap + 32);
                uint32_t a10 = __ldg(ap + 64);
                uint32_t a11 = __ldg(ap + 96);
                const uint32_t* bU = bB + (ks * 4 + tq) * BST2;
                #pragma unroll
                for (int nt = 0; nt < 8; nt++) {
                    uint32_t b0 = bU[nt * 8];
                    mma_f16(acc[0][nt], a00, a01, b0);
                    mma_f16(acc[1][nt], a10, a11, b0);
                }
            }
        }

        if (s == NSTEP - 1) break;
        const int sp = s + 1;
        const int pcg = sp / 3, ptb = sp - pcg * 3;

        if (warp < 6) {
            const uint32_t* xw = sX + (pcg & 1) * XWIN2;
            const float* xcb = xg + pcg * 8 * 4096;
            uint32_t* bD = sBu + (sp & 1) * BBUF;
            gather_unit(xw, xcb, bD, sMI, sMW, t, ptb, lo);
            gather_unit(xw, xcb, bD, sMI, sMW, 192 + t, ptb, lo);
        } else {
            int s3q = s / 3, s3r = s - s3q * 3;
            if (s3r < 2 && s3q + 1 < 16) {
                const int c = s3q + 1;
                uint32_t* xwn = sX + (c & 1) * XWIN2;
                const float* xcb = xg + c * 8 * 4096;
                int t2 = t - 192;
                #pragma unroll
                for (int j = 0; j < XROWS; j++)
                    stage_unit(xwn, xcb, s3r * (XROWS * 64) + t2 + j * 64, lo);
            }
        }
    }

    // ---- epilogue: D[m=cout][n = warpN*64 + nt*8 + 2tq] -> out row 2*ho2+warpN ----
    float* o = out + b * 524288 + (2 * ho2 + warpN) * 64;
    #pragma unroll
    for (int mt = 0; mt < 2; mt++) {
        int row0 = warpM * 32 + mt * 16 + g;
        #pragma unroll
        for (int nt = 0; nt < 8; nt++) {
            int p = nt * 8 + 2 * tq;
            *(float2*)(o + row0 * 4096 + p) =
                make_float2(acc[mt][nt][0], acc[mt][nt][1]);
            *(float2*)(o + (row0 + 8) * 4096 + p) =
                make_float2(acc[mt][nt][2], acc[mt][nt][3]);
        }
    }
}

extern "C" void kernel_launch(void* const* d_in, const int* in_sizes, int n_in,
                              void* d_out, int out_size) {
    const float* x    = (const float*)d_in[0];
    const float* offs = (const float*)d_in[1];
    const float* wgt  = (const float*)d_in[2];
    wt_permute<<<(NSTEP * 3 * 128 * 4 + 255) / 256, 256>>>(wgt);
    cudaFuncSetAttribute(deform_conv_f16w,
                         cudaFuncAttributeMaxDynamicSharedMemorySize, SMEM_TOTAL);
    deform_conv_f16w<<<256, THREADS, SMEM_TOTAL>>>(x, offs, (float*)d_out);
}